// round 14
// baseline (speedup 1.0000x reference)
#include <cuda_runtime.h>
#include <math.h>

// GRU problem constants
#define T_SEQ 1024
#define BATCH 32
#define HID   512
#define H3    1536   // 3*HID
#define LAYERS 3

// ---------------------------------------------------------------------------
// Scratch (device globals — no runtime allocation allowed)
// ---------------------------------------------------------------------------
__device__ float g_xi[2][T_SEQ][H3][BATCH];     // [dir][t][gate_row][batch]
__device__ float g_y[2][T_SEQ][BATCH][2 * HID]; // layer outputs (2 buffers)
__device__ float g_h[2][2][BATCH][HID];         // h dbl buffer (fallback path)
__device__ int   g_flag[2][4][32];              // epoch flags (fallback path)

typedef unsigned long long ull;

// ---------------------------------------------------------------------------
// f32x2 packed-FMA helpers (sm_100+; only reachable via PTX)
// ---------------------------------------------------------------------------
__device__ __forceinline__ ull dup2(float x) {
    ull r;
    asm("mov.b64 %0, {%1, %1};" : "=l"(r) : "f"(x));
    return r;
}
__device__ __forceinline__ void ffma2(ull& d, ull a, ull b) {
    asm("fma.rn.f32x2 %0, %1, %2, %0;" : "+l"(d) : "l"(a), "l"(b));
}
__device__ __forceinline__ float2 unpk(ull v) {
    float2 f;
    asm("mov.b64 {%0, %1}, %2;" : "=f"(f.x), "=f"(f.y) : "l"(v));
    return f;
}
__device__ __forceinline__ unsigned smem_u32(const void* p) {
    unsigned a;
    asm("{ .reg .u64 t; cvta.to.shared.u64 t, %1; cvt.u32.u64 %0, t; }"
        : "=r"(a) : "l"(p));
    return a;
}

// ---------------------------------------------------------------------------
// Zero the flag array (needed by the fallback gru path)
// ---------------------------------------------------------------------------
__global__ void zero_bar_kernel() {
    int i = threadIdx.x;
    if (i < 2 * 4 * 32) ((int*)g_flag)[i] = 0;
}

// ---------------------------------------------------------------------------
// Input projection (R12 8x8 — best measured): 128x128 tile, 256 threads,
// 8m x 8j per thread, register double-buffered loads, f32x2 packed FMA.
// ---------------------------------------------------------------------------
__global__ __launch_bounds__(256) void proj_kernel(
    const float* __restrict__ x0,
    const float* __restrict__ W,      // (2, 1536, K)
    const float* __restrict__ bih,    // (2, 1536)
    int K, int src)
{
    const float* A = (src == 0) ? x0 : &g_y[src - 1][0][0][0];

    int d  = blockIdx.z;
    int n0 = blockIdx.x * 128;  // gate-row tile
    int m0 = blockIdx.y * 128;  // (t,b) row tile
    const float* Wd = W + (size_t)d * H3 * K;
    const float* bd = bih + d * H3;

    __shared__ float As[16][128];
    __shared__ float Bs[16][128];

    int tid = threadIdx.x;
    int tx  = tid & 15;
    int ty  = tid >> 4;

    int i0    = tid;
    int lrow0 = i0 >> 2, lq0 = (i0 & 3) << 2;
    int i1    = 256 + tid;
    int lrow1 = i1 >> 2, lq1 = (i1 & 3) << 2;

    const float* Ap0 = &A [(size_t)(m0 + lrow0) * K + lq0];
    const float* Ap1 = &A [(size_t)(m0 + lrow1) * K + lq1];
    const float* Wp0 = &Wd[(size_t)(n0 + lrow0) * K + lq0];
    const float* Wp1 = &Wd[(size_t)(n0 + lrow1) * K + lq1];

    ull acc[8][4];
#pragma unroll
    for (int i = 0; i < 8; i++)
#pragma unroll
        for (int j = 0; j < 4; j++) acc[i][j] = 0ull;

    float4 a0_nx = *(const float4*)Ap0;
    float4 a1_nx = *(const float4*)Ap1;
    float4 b0_nx = *(const float4*)Wp0;
    float4 b1_nx = *(const float4*)Wp1;

    for (int k0 = 0; k0 < K; k0 += 16) {
        As[lq0 + 0][lrow0] = a0_nx.x; As[lq0 + 1][lrow0] = a0_nx.y;
        As[lq0 + 2][lrow0] = a0_nx.z; As[lq0 + 3][lrow0] = a0_nx.w;
        As[lq1 + 0][lrow1] = a1_nx.x; As[lq1 + 1][lrow1] = a1_nx.y;
        As[lq1 + 2][lrow1] = a1_nx.z; As[lq1 + 3][lrow1] = a1_nx.w;
        Bs[lq0 + 0][lrow0] = b0_nx.x; Bs[lq0 + 1][lrow0] = b0_nx.y;
        Bs[lq0 + 2][lrow0] = b0_nx.z; Bs[lq0 + 3][lrow0] = b0_nx.w;
        Bs[lq1 + 0][lrow1] = b1_nx.x; Bs[lq1 + 1][lrow1] = b1_nx.y;
        Bs[lq1 + 2][lrow1] = b1_nx.z; Bs[lq1 + 3][lrow1] = b1_nx.w;
        __syncthreads();

        if (k0 + 16 < K) {
            a0_nx = *(const float4*)(Ap0 + k0 + 16);
            a1_nx = *(const float4*)(Ap1 + k0 + 16);
            b0_nx = *(const float4*)(Wp0 + k0 + 16);
            b1_nx = *(const float4*)(Wp1 + k0 + 16);
        }

#pragma unroll
        for (int kk = 0; kk < 16; kk++) {
            float4 af0 = *(const float4*)&As[kk][ty * 4];
            float4 af1 = *(const float4*)&As[kk][64 + ty * 4];
            ulonglong2 b0 = *(const ulonglong2*)&Bs[kk][tx * 4];
            ulonglong2 b1 = *(const ulonglong2*)&Bs[kk][64 + tx * 4];
            ull aa[8];
            aa[0] = dup2(af0.x); aa[1] = dup2(af0.y);
            aa[2] = dup2(af0.z); aa[3] = dup2(af0.w);
            aa[4] = dup2(af1.x); aa[5] = dup2(af1.y);
            aa[6] = dup2(af1.z); aa[7] = dup2(af1.w);
#pragma unroll
            for (int i = 0; i < 8; i++) {
                ffma2(acc[i][0], aa[i], b0.x);
                ffma2(acc[i][1], aa[i], b0.y);
                ffma2(acc[i][2], aa[i], b1.x);
                ffma2(acc[i][3], aa[i], b1.y);
            }
        }
        __syncthreads();
    }

#pragma unroll
    for (int i = 0; i < 8; i++) {
        int m = m0 + ((i < 4) ? (ty * 4 + i) : (64 + ty * 4 + (i - 4)));
        int t = m >> 5;
        int b = m & 31;
#pragma unroll
        for (int jp = 0; jp < 4; jp++) {
            int g = n0 + ((jp < 2) ? (tx * 4 + jp * 2)
                                   : (64 + tx * 4 + (jp - 2) * 2));
            float2 c = unpk(acc[i][jp]);
            g_xi[d][t][g + 0][b] = c.x + bd[g + 0];
            g_xi[d][t][g + 1][b] = c.y + bd[g + 1];
        }
    }
}

// ===========================================================================
// GRU v6 — 16-CTA CLUSTER + DSMEM all-to-all h exchange.
// grid (16,4,2), cluster {16,1,1}: one cluster = one (dir, batch-octet)
// exchange group. Reg-resident W_hh as before. Per step: GEMV from local
// sH[s&1] -> gates -> push own 1KB slice into ALL 16 CTAs' sH[(s+1)&1] via
// st.shared::cluster (float4, shfl-packed) -> barrier.cluster (Xi prefetch
// between arrive and wait). No g_h, no flags, no __syncthreads in the loop.
// ===========================================================================
__global__ __launch_bounds__(256) void gru_layer_cluster(
    const float* __restrict__ whh,   // (2, 1536, 512)
    const float* __restrict__ bhh,   // (2, 1536)
    float* __restrict__ dout,        // (6, 32, 512)
    int layer, int ydst)
{
    __shared__ __align__(16) float sH[2][8 * HID];   // 32KB double-buffered h

    int ctax = blockIdx.x;           // == cluster rank (cluster spans x)
    int grp  = blockIdx.y;
    int d    = blockIdx.z;
    int tid  = threadIdx.x;
    int w    = tid >> 5;
    int l    = tid & 31;
    int lj   = l & 3;                // j-row within quad
    int lks  = l >> 2;               // k-slice / batch-in-group
    int j    = ctax * 32 + w * 4 + lj;
    int b_ep = grp * 8 + lks;

    unsigned shbase = smem_u32(&sH[0][0]);

    // ---- Load W_hh into registers (once per layer) ----
    ull Wr[32], Wz[32], Wn[32];
    {
        const float* wd = whh + (size_t)d * H3 * HID;
        const float* pr = &wd[(size_t)(0 * 512 + j) * 512 + lks * 4];
        const float* pz = &wd[(size_t)(1 * 512 + j) * 512 + lks * 4];
        const float* pn = &wd[(size_t)(2 * 512 + j) * 512 + lks * 4];
#pragma unroll
        for (int i = 0; i < 16; i++) {
            ulonglong2 v;
            v = *(const ulonglong2*)&pr[i * 32];
            Wr[2 * i] = v.x; Wr[2 * i + 1] = v.y;
            v = *(const ulonglong2*)&pz[i * 32];
            Wz[2 * i] = v.x; Wz[2 * i + 1] = v.y;
            v = *(const ulonglong2*)&pn[i * 32];
            Wn[2 * i] = v.x; Wn[2 * i + 1] = v.y;
        }
    }
    const float* bd = bhh + d * H3;
    float br = bd[j], bz = bd[512 + j], bn = bd[1024 + j];

    float hold = 0.f;
    int t0 = d ? (T_SEQ - 1) : 0;
    float xr = g_xi[d][t0][j][b_ep];
    float xz = g_xi[d][t0][512 + j][b_ep];
    float xn = g_xi[d][t0][1024 + j][b_ep];

    for (int s = 0; s < T_SEQ; s++) {
        int t = d ? (T_SEQ - 1 - s) : s;

        float arS = 0.f, azS = 0.f, anS = 0.f;
        if (s > 0) {
            const float* hbuf = &sH[s & 1][0];
            for (int b = 0; b < 8; b++) {
                const float* hp = &hbuf[b * HID + lks * 4];
                ull a0 = 0ull, a1 = 0ull, a2 = 0ull;
#pragma unroll
                for (int i = 0; i < 16; i++) {
                    ulonglong2 hh = *(const ulonglong2*)&hp[i * 32];
                    ffma2(a0, Wr[2 * i], hh.x); ffma2(a0, Wr[2 * i + 1], hh.y);
                    ffma2(a1, Wz[2 * i], hh.x); ffma2(a1, Wz[2 * i + 1], hh.y);
                    ffma2(a2, Wn[2 * i], hh.x); ffma2(a2, Wn[2 * i + 1], hh.y);
                }
                float2 f0 = unpk(a0), f1 = unpk(a1), f2 = unpk(a2);
                float ar = f0.x + f0.y;
                float az = f1.x + f1.y;
                float an = f2.x + f2.y;
#pragma unroll
                for (int m = 4; m <= 16; m <<= 1) {
                    ar += __shfl_xor_sync(0xffffffffu, ar, m);
                    az += __shfl_xor_sync(0xffffffffu, az, m);
                    an += __shfl_xor_sync(0xffffffffu, an, m);
                }
                if (lks == b) { arS = ar; azS = az; anS = an; }
            }
        }

        float r = 1.f / (1.f + __expf(-(xr + arS + br)));
        float z = 1.f / (1.f + __expf(-(xz + azS + bz)));
        float n = tanhf(xn + r * (anS + bn));
        float hnew = (1.f - z) * n + z * hold;
        hold = hnew;

        g_y[ydst][t][b_ep][d * HID + j] = hnew;

        if (s == T_SEQ - 1) {
            dout[((layer * 2 + d) * BATCH + b_ep) * HID + j] = hnew;
            break;   // all cluster CTAs break together — no barrier pending
        }

        // ---- DSMEM all-to-all: push own (b=lks, j..j+3) into every CTA ----
        float v1 = __shfl_down_sync(0xffffffffu, hnew, 1);
        float v2 = __shfl_down_sync(0xffffffffu, hnew, 2);
        float v3 = __shfl_down_sync(0xffffffffu, hnew, 3);
        if (lj == 0) {
            unsigned u0 = __float_as_uint(hnew);
            unsigned u1 = __float_as_uint(v1);
            unsigned u2 = __float_as_uint(v2);
            unsigned u3 = __float_as_uint(v3);
            unsigned loc = shbase +
                ((((s + 1) & 1) * 8 * HID) + lks * HID + ctax * 32 + w * 4) * 4;
#pragma unroll
            for (int rk = 0; rk < 16; rk++) {
                unsigned rem;
                asm("mapa.shared::cluster.u32 %0, %1, %2;"
                    : "=r"(rem) : "r"(loc), "r"(rk));
                asm volatile(
                    "st.shared::cluster.v4.b32 [%0], {%1, %2, %3, %4};"
                    :: "r"(rem), "r"(u0), "r"(u1), "r"(u2), "r"(u3)
                    : "memory");
            }
        }

        // ---- Cluster barrier; Xi prefetch issued between arrive and wait ----
        asm volatile("barrier.cluster.arrive.aligned;" ::: "memory");
        int tn = d ? (T_SEQ - 2 - s) : (s + 1);
        float nxr = g_xi[d][tn][j][b_ep];
        float nxz = g_xi[d][tn][512 + j][b_ep];
        float nxn = g_xi[d][tn][1024 + j][b_ep];
        asm volatile("barrier.cluster.wait.aligned;" ::: "memory");
        xr = nxr; xz = nxz; xn = nxn;
    }
}

// ---------------------------------------------------------------------------
// Fallback GRU (R11/R13 flags version — known correct, 5.4ms/layer)
// ---------------------------------------------------------------------------
__global__ __launch_bounds__(256) void gru_layer_kernel(
    const float* __restrict__ whh,
    const float* __restrict__ bhh,
    float* __restrict__ dout,
    int layer, int ydst)
{
    __shared__ float sH[8 * HID];

    int ctax = blockIdx.x;
    int grp  = blockIdx.y;
    int d    = blockIdx.z;
    int tid  = threadIdx.x;
    int w    = tid >> 5;
    int l    = tid & 31;
    int lj   = l & 3;
    int lks  = l >> 2;
    int j    = ctax * 32 + w * 4 + lj;
    int b_ep = grp * 8 + lks;

    ull Wr[32], Wz[32], Wn[32];
    {
        const float* wd = whh + (size_t)d * H3 * HID;
        const float* pr = &wd[(size_t)(0 * 512 + j) * 512 + lks * 4];
        const float* pz = &wd[(size_t)(1 * 512 + j) * 512 + lks * 4];
        const float* pn = &wd[(size_t)(2 * 512 + j) * 512 + lks * 4];
#pragma unroll
        for (int i = 0; i < 16; i++) {
            ulonglong2 v;
            v = *(const ulonglong2*)&pr[i * 32];
            Wr[2 * i] = v.x; Wr[2 * i + 1] = v.y;
            v = *(const ulonglong2*)&pz[i * 32];
            Wz[2 * i] = v.x; Wz[2 * i + 1] = v.y;
            v = *(const ulonglong2*)&pn[i * 32];
            Wn[2 * i] = v.x; Wn[2 * i + 1] = v.y;
        }
    }
    const float* bd = bhh + d * H3;
    float br = bd[j], bz = bd[512 + j], bn = bd[1024 + j];

    volatile int* flags = &g_flag[d][grp][0];
    float hold = 0.f;
    int t0 = d ? (T_SEQ - 1) : 0;
    float xr = g_xi[d][t0][j][b_ep];
    float xz = g_xi[d][t0][512 + j][b_ep];
    float xn = g_xi[d][t0][1024 + j][b_ep];

    for (int s = 0; s < T_SEQ; s++) {
        int t = d ? (T_SEQ - 1 - s) : s;

        float arS = 0.f, azS = 0.f, anS = 0.f;
        if (s > 0) {
            const float* hin = &g_h[s & 1][d][grp * 8][0];
#pragma unroll
            for (int it = 0; it < 4; it++) {
                int idx = it * 256 + tid;
                float4 v = __ldcg((const float4*)&hin[idx << 2]);
                *(float4*)&sH[idx << 2] = v;
            }
            __syncthreads();

            for (int b = 0; b < 8; b++) {
                const float* hp = &sH[b * HID + lks * 4];
                ull a0 = 0ull, a1 = 0ull, a2 = 0ull;
#pragma unroll
                for (int i = 0; i < 16; i++) {
                    ulonglong2 hh = *(const ulonglong2*)&hp[i * 32];
                    ffma2(a0, Wr[2 * i], hh.x); ffma2(a0, Wr[2 * i + 1], hh.y);
                    ffma2(a1, Wz[2 * i], hh.x); ffma2(a1, Wz[2 * i + 1], hh.y);
                    ffma2(a2, Wn[2 * i], hh.x); ffma2(a2, Wn[2 * i + 1], hh.y);
                }
                float2 f0 = unpk(a0), f1 = unpk(a1), f2 = unpk(a2);
                float ar = f0.x + f0.y;
                float az = f1.x + f1.y;
                float an = f2.x + f2.y;
#pragma unroll
                for (int m = 4; m <= 16; m <<= 1) {
                    ar += __shfl_xor_sync(0xffffffffu, ar, m);
                    az += __shfl_xor_sync(0xffffffffu, az, m);
                    an += __shfl_xor_sync(0xffffffffu, an, m);
                }
                if (lks == b) { arS = ar; azS = az; anS = an; }
            }
        }

        float r = 1.f / (1.f + __expf(-(xr + arS + br)));
        float z = 1.f / (1.f + __expf(-(xz + azS + bz)));
        float n = tanhf(xn + r * (anS + bn));
        float hnew = (1.f - z) * n + z * hold;
        hold = hnew;

        g_h[(s & 1) ^ 1][d][b_ep][j] = hnew;
        g_y[ydst][t][b_ep][d * HID + j] = hnew;

        if (s == T_SEQ - 1) {
            dout[((layer * 2 + d) * BATCH + b_ep) * HID + j] = hnew;
            break;
        }

        __syncthreads();
        int e = layer * T_SEQ + s + 1;
        if (tid == 0) {
            __threadfence();
            flags[ctax] = e;
        }
        int tn = d ? (T_SEQ - 2 - s) : (s + 1);
        float nxr = g_xi[d][tn][j][b_ep];
        float nxz = g_xi[d][tn][512 + j][b_ep];
        float nxn = g_xi[d][tn][1024 + j][b_ep];
        if (tid < 16) {
            while (flags[tid] < e) { }
            __threadfence();
        }
        __syncthreads();
        xr = nxr; xz = nxz; xn = nxn;
    }
}

// ---------------------------------------------------------------------------
// kernel_launch: proj0, zero, zero(dummy), gru0, proj1, gru1, proj2, gru2
// (8 nodes; ncu -s 5 -c 1 lands on gru1)
// ---------------------------------------------------------------------------
extern "C" void kernel_launch(void* const* d_in, const int* in_sizes, int n_in,
                              void* d_out, int out_size)
{
    const float* x        = (const float*)d_in[0];
    const float* w_ih_l0  = (const float*)d_in[1];
    const float* w_hh_l0  = (const float*)d_in[2];
    const float* b_ih_l0  = (const float*)d_in[3];
    const float* b_hh_l0  = (const float*)d_in[4];
    const float* w_ih_lr  = (const float*)d_in[5];
    const float* w_hh_lr  = (const float*)d_in[6];
    const float* b_ih_lr  = (const float*)d_in[7];
    const float* b_hh_lr  = (const float*)d_in[8];
    float* out = (float*)d_out;

    const float* WI[LAYERS];
    const float* WH[LAYERS];
    const float* BI[LAYERS];
    const float* BH[LAYERS];
    int KK[LAYERS], SRC[LAYERS], YD[LAYERS];
    for (int L = 0; L < LAYERS; L++) {
        if (L == 0) {
            WI[L] = w_ih_l0; WH[L] = w_hh_l0; BI[L] = b_ih_l0; BH[L] = b_hh_l0;
            KK[L] = 256; SRC[L] = 0;
        } else {
            WI[L] = w_ih_lr + (size_t)(L - 1) * 2 * H3 * 1024;
            WH[L] = w_hh_lr + (size_t)(L - 1) * 2 * H3 * HID;
            BI[L] = b_ih_lr + (L - 1) * 2 * H3;
            BH[L] = b_hh_lr + (L - 1) * 2 * H3;
            KK[L] = 1024; SRC[L] = L;
        }
        YD[L] = (L == 1) ? 1 : 0;
    }

    dim3 pg(H3 / 128, (T_SEQ * BATCH) / 128, 2);
    dim3 gg(16, 4, 2);   // (j-slice / cluster rank, group, dir)

    // Cluster setup: 16-CTA nonportable cluster; fall back to flags kernel.
    cudaFuncSetAttribute(gru_layer_cluster,
                         cudaFuncAttributeNonPortableClusterSizeAllowed, 1);
    cudaLaunchConfig_t cfg = {};
    cfg.gridDim  = gg;
    cfg.blockDim = dim3(256, 1, 1);
    cfg.dynamicSmemBytes = 0;
    cfg.stream = 0;
    cudaLaunchAttribute at[1];
    at[0].id = cudaLaunchAttributeClusterDimension;
    at[0].val.clusterDim.x = 16;
    at[0].val.clusterDim.y = 1;
    at[0].val.clusterDim.z = 1;
    cfg.attrs = at;
    cfg.numAttrs = 1;

    int maxC = 0;
    {
        cudaLaunchConfig_t q = {};
        q.gridDim  = gg;
        q.blockDim = dim3(256, 1, 1);
        q.dynamicSmemBytes = 0;
        cudaOccupancyMaxPotentialClusterSize(&maxC, gru_layer_cluster, &q);
    }
    bool useClu = (maxC >= 16);

    proj_kernel<<<pg, 256>>>(x, WI[0], BI[0], KK[0], SRC[0]);
    zero_bar_kernel<<<1, 256>>>();
    zero_bar_kernel<<<1, 256>>>();   // dummy: aligns ncu -s 5 on gru1

    for (int L = 0; L < LAYERS; L++) {
        if (L > 0)
            proj_kernel<<<pg, 256>>>(x, WI[L], BI[L], KK[L], SRC[L]);
        if (useClu)
            cudaLaunchKernelEx(&cfg, gru_layer_cluster,
                               WH[L], BH[L], out, L, YD[L]);
        else
            gru_layer_kernel<<<gg, 256>>>(WH[L], BH[L], out, L, YD[L]);
    }
}

// round 15
// speedup vs baseline: 1.4491x; 1.4491x over previous
#include <cuda_runtime.h>
#include <math.h>

// GRU problem constants
#define T_SEQ 1024
#define BATCH 32
#define HID   512
#define H3    1536   // 3*HID
#define LAYERS 3

// ---------------------------------------------------------------------------
// Scratch (device globals — no runtime allocation allowed)
// ---------------------------------------------------------------------------
__device__ float g_xi[2][T_SEQ][H3][BATCH];     // [dir][t][gate_row][batch]
__device__ float g_y[2][T_SEQ][BATCH][2 * HID]; // layer outputs (2 buffers)
__device__ float g_h[2][2][BATCH][HID];         // h double buffer [buf][dir][b][k]
__device__ int   g_flag[2][4][32];              // [dir][group][cta] epoch flags

typedef unsigned long long ull;

// ---------------------------------------------------------------------------
// f32x2 packed-FMA helpers (sm_100+; only reachable via PTX)
// ---------------------------------------------------------------------------
__device__ __forceinline__ ull dup2(float x) {
    ull r;
    asm("mov.b64 %0, {%1, %1};" : "=l"(r) : "f"(x));
    return r;
}
__device__ __forceinline__ void ffma2(ull& d, ull a, ull b) {
    asm("fma.rn.f32x2 %0, %1, %2, %0;" : "+l"(d) : "l"(a), "l"(b));
}
__device__ __forceinline__ float2 unpk(ull v) {
    float2 f;
    asm("mov.b64 {%0, %1}, %2;" : "=f"(f.x), "=f"(f.y) : "l"(v));
    return f;
}

// ---------------------------------------------------------------------------
// Zero the flag array (runs once per graph replay, before gru0)
// ---------------------------------------------------------------------------
__global__ void zero_bar_kernel() {
    int i = threadIdx.x;
    if (i < 2 * 4 * 32) ((int*)g_flag)[i] = 0;
}

// ---------------------------------------------------------------------------
// Input projection (R12 8x8 — best measured): 128x128 tile, 256 threads,
// 8m x 8j per thread, register double-buffered loads, f32x2 packed FMA.
// ---------------------------------------------------------------------------
__global__ __launch_bounds__(256) void proj_kernel(
    const float* __restrict__ x0,
    const float* __restrict__ W,      // (2, 1536, K)
    const float* __restrict__ bih,    // (2, 1536)
    int K, int src)
{
    const float* A = (src == 0) ? x0 : &g_y[src - 1][0][0][0];

    int d  = blockIdx.z;
    int n0 = blockIdx.x * 128;  // gate-row tile
    int m0 = blockIdx.y * 128;  // (t,b) row tile
    const float* Wd = W + (size_t)d * H3 * K;
    const float* bd = bih + d * H3;

    __shared__ float As[16][128];
    __shared__ float Bs[16][128];

    int tid = threadIdx.x;
    int tx  = tid & 15;
    int ty  = tid >> 4;

    int i0    = tid;
    int lrow0 = i0 >> 2, lq0 = (i0 & 3) << 2;
    int i1    = 256 + tid;
    int lrow1 = i1 >> 2, lq1 = (i1 & 3) << 2;

    const float* Ap0 = &A [(size_t)(m0 + lrow0) * K + lq0];
    const float* Ap1 = &A [(size_t)(m0 + lrow1) * K + lq1];
    const float* Wp0 = &Wd[(size_t)(n0 + lrow0) * K + lq0];
    const float* Wp1 = &Wd[(size_t)(n0 + lrow1) * K + lq1];

    ull acc[8][4];
#pragma unroll
    for (int i = 0; i < 8; i++)
#pragma unroll
        for (int j = 0; j < 4; j++) acc[i][j] = 0ull;

    float4 a0_nx = *(const float4*)Ap0;
    float4 a1_nx = *(const float4*)Ap1;
    float4 b0_nx = *(const float4*)Wp0;
    float4 b1_nx = *(const float4*)Wp1;

    for (int k0 = 0; k0 < K; k0 += 16) {
        As[lq0 + 0][lrow0] = a0_nx.x; As[lq0 + 1][lrow0] = a0_nx.y;
        As[lq0 + 2][lrow0] = a0_nx.z; As[lq0 + 3][lrow0] = a0_nx.w;
        As[lq1 + 0][lrow1] = a1_nx.x; As[lq1 + 1][lrow1] = a1_nx.y;
        As[lq1 + 2][lrow1] = a1_nx.z; As[lq1 + 3][lrow1] = a1_nx.w;
        Bs[lq0 + 0][lrow0] = b0_nx.x; Bs[lq0 + 1][lrow0] = b0_nx.y;
        Bs[lq0 + 2][lrow0] = b0_nx.z; Bs[lq0 + 3][lrow0] = b0_nx.w;
        Bs[lq1 + 0][lrow1] = b1_nx.x; Bs[lq1 + 1][lrow1] = b1_nx.y;
        Bs[lq1 + 2][lrow1] = b1_nx.z; Bs[lq1 + 3][lrow1] = b1_nx.w;
        __syncthreads();

        if (k0 + 16 < K) {
            a0_nx = *(const float4*)(Ap0 + k0 + 16);
            a1_nx = *(const float4*)(Ap1 + k0 + 16);
            b0_nx = *(const float4*)(Wp0 + k0 + 16);
            b1_nx = *(const float4*)(Wp1 + k0 + 16);
        }

#pragma unroll
        for (int kk = 0; kk < 16; kk++) {
            float4 af0 = *(const float4*)&As[kk][ty * 4];
            float4 af1 = *(const float4*)&As[kk][64 + ty * 4];
            ulonglong2 b0 = *(const ulonglong2*)&Bs[kk][tx * 4];
            ulonglong2 b1 = *(const ulonglong2*)&Bs[kk][64 + tx * 4];
            ull aa[8];
            aa[0] = dup2(af0.x); aa[1] = dup2(af0.y);
            aa[2] = dup2(af0.z); aa[3] = dup2(af0.w);
            aa[4] = dup2(af1.x); aa[5] = dup2(af1.y);
            aa[6] = dup2(af1.z); aa[7] = dup2(af1.w);
#pragma unroll
            for (int i = 0; i < 8; i++) {
                ffma2(acc[i][0], aa[i], b0.x);
                ffma2(acc[i][1], aa[i], b0.y);
                ffma2(acc[i][2], aa[i], b1.x);
                ffma2(acc[i][3], aa[i], b1.y);
            }
        }
        __syncthreads();
    }

#pragma unroll
    for (int i = 0; i < 8; i++) {
        int m = m0 + ((i < 4) ? (ty * 4 + i) : (64 + ty * 4 + (i - 4)));
        int t = m >> 5;
        int b = m & 31;
#pragma unroll
        for (int jp = 0; jp < 4; jp++) {
            int g = n0 + ((jp < 2) ? (tx * 4 + jp * 2)
                                   : (64 + tx * 4 + (jp - 2) * 2));
            float2 c = unpk(acc[i][jp]);
            g_xi[d][t][g + 0][b] = c.x + bd[g + 0];
            g_xi[d][t][g + 1][b] = c.y + bd[g + 1];
        }
    }
}

// ---------------------------------------------------------------------------
// Persistent recurrent kernel (R11/R13 structure — best measured).
// Register-resident W_hh; L2 flags exchange; __expf gates; batch loop
// interleaved x2 for shfl/LDS latency hiding.
// ---------------------------------------------------------------------------
__global__ __launch_bounds__(256) void gru_layer_kernel(
    const float* __restrict__ whh,   // (2, 1536, 512)
    const float* __restrict__ bhh,   // (2, 1536)
    float* __restrict__ dout,        // (6, 32, 512)
    int layer, int ydst)
{
    __shared__ float sH[8 * HID];    // 16KB h staging [b_in_group][k]

    int ctax = blockIdx.x;           // 0..15 : j-slice (32 j each)
    int grp  = blockIdx.y;           // 0..3  : batch octet
    int d    = blockIdx.z;           // direction
    int tid  = threadIdx.x;
    int w    = tid >> 5;
    int l    = tid & 31;
    int lj   = l & 3;                // j-row within quad
    int lks  = l >> 2;               // k-slice 0..7
    int j    = ctax * 32 + w * 4 + lj;   // global j (this thread's row)
    int b_ep = grp * 8 + lks;        // epilogue batch

    // ---- Load W_hh into registers (once per layer) ----
    ull Wr[32], Wz[32], Wn[32];
    {
        const float* wd = whh + (size_t)d * H3 * HID;
        const float* pr = &wd[(size_t)(0 * 512 + j) * 512 + lks * 4];
        const float* pz = &wd[(size_t)(1 * 512 + j) * 512 + lks * 4];
        const float* pn = &wd[(size_t)(2 * 512 + j) * 512 + lks * 4];
#pragma unroll
        for (int i = 0; i < 16; i++) {
            ulonglong2 v;
            v = *(const ulonglong2*)&pr[i * 32];
            Wr[2 * i] = v.x; Wr[2 * i + 1] = v.y;
            v = *(const ulonglong2*)&pz[i * 32];
            Wz[2 * i] = v.x; Wz[2 * i + 1] = v.y;
            v = *(const ulonglong2*)&pn[i * 32];
            Wn[2 * i] = v.x; Wn[2 * i + 1] = v.y;
        }
    }
    const float* bd = bhh + d * H3;
    float br = bd[j], bz = bd[512 + j], bn = bd[1024 + j];

    volatile int* flags = &g_flag[d][grp][0];
    float hold = 0.f;
    int t0 = d ? (T_SEQ - 1) : 0;
    float xr = g_xi[d][t0][j][b_ep];
    float xz = g_xi[d][t0][512 + j][b_ep];
    float xn = g_xi[d][t0][1024 + j][b_ep];

    for (int s = 0; s < T_SEQ; s++) {
        int t = d ? (T_SEQ - 1 - s) : s;

        float arS = 0.f, azS = 0.f, anS = 0.f;
        if (s > 0) {
            // Stage group's h: 8 rows x 512 = 1024 float4 -> 4 per thread
            const float* hin = &g_h[s & 1][d][grp * 8][0];
#pragma unroll
            for (int it = 0; it < 4; it++) {
                int idx = it * 256 + tid;            // float4 units, 0..1023
                float4 v = __ldcg((const float4*)&hin[idx << 2]);
                *(float4*)&sH[idx << 2] = v;
            }
            __syncthreads();

            // GEMV: 2 batches interleaved (hides LDS + shfl latency).
            // Per pair: partials over this thread's strided k-slice, then
            // butterfly-reduce over lks; keep the b == lks results.
#pragma unroll
            for (int bp = 0; bp < 4; bp++) {
                int bA = bp * 2, bB = bp * 2 + 1;
                const float* hpA = &sH[bA * HID + lks * 4];
                const float* hpB = &sH[bB * HID + lks * 4];
                ull aA0 = 0ull, aA1 = 0ull, aA2 = 0ull;
                ull aB0 = 0ull, aB1 = 0ull, aB2 = 0ull;
#pragma unroll
                for (int i = 0; i < 16; i++) {
                    ulonglong2 hA = *(const ulonglong2*)&hpA[i * 32];
                    ulonglong2 hB = *(const ulonglong2*)&hpB[i * 32];
                    ffma2(aA0, Wr[2 * i], hA.x); ffma2(aA0, Wr[2 * i + 1], hA.y);
                    ffma2(aB0, Wr[2 * i], hB.x); ffma2(aB0, Wr[2 * i + 1], hB.y);
                    ffma2(aA1, Wz[2 * i], hA.x); ffma2(aA1, Wz[2 * i + 1], hA.y);
                    ffma2(aB1, Wz[2 * i], hB.x); ffma2(aB1, Wz[2 * i + 1], hB.y);
                    ffma2(aA2, Wn[2 * i], hA.x); ffma2(aA2, Wn[2 * i + 1], hA.y);
                    ffma2(aB2, Wn[2 * i], hB.x); ffma2(aB2, Wn[2 * i + 1], hB.y);
                }
                float2 f;
                f = unpk(aA0); float arA = f.x + f.y;
                f = unpk(aA1); float azA = f.x + f.y;
                f = unpk(aA2); float anA = f.x + f.y;
                f = unpk(aB0); float arB = f.x + f.y;
                f = unpk(aB1); float azB = f.x + f.y;
                f = unpk(aB2); float anB = f.x + f.y;
#pragma unroll
                for (int m = 4; m <= 16; m <<= 1) {
                    arA += __shfl_xor_sync(0xffffffffu, arA, m);
                    azA += __shfl_xor_sync(0xffffffffu, azA, m);
                    anA += __shfl_xor_sync(0xffffffffu, anA, m);
                    arB += __shfl_xor_sync(0xffffffffu, arB, m);
                    azB += __shfl_xor_sync(0xffffffffu, azB, m);
                    anB += __shfl_xor_sync(0xffffffffu, anB, m);
                }
                if (lks == bA) { arS = arA; azS = azA; anS = anA; }
                if (lks == bB) { arS = arB; azS = azB; anS = anB; }
            }
        }

        float r = 1.f / (1.f + __expf(-(xr + arS + br)));
        float z = 1.f / (1.f + __expf(-(xz + azS + bz)));
        float n = tanhf(xn + r * (anS + bn));
        float hnew = (1.f - z) * n + z * hold;
        hold = hnew;

        g_h[(s & 1) ^ 1][d][b_ep][j] = hnew;
        g_y[ydst][t][b_ep][d * HID + j] = hnew;

        if (s == T_SEQ - 1) {
            dout[((layer * 2 + d) * BATCH + b_ep) * HID + j] = hnew;
            break;   // nothing consumes h after the last step
        }

        // ---- Group barrier: 16 CTAs, per-CTA epoch flags ----
        __syncthreads();                 // h stores issued; sH reads done
        int e = layer * T_SEQ + s + 1;   // monotonic across layers
        if (tid == 0) {
            __threadfence();             // order this CTA's h stores
            flags[ctax] = e;
        }
        // Prefetch next step's Xi while flags propagate
        int tn = d ? (T_SEQ - 2 - s) : (s + 1);
        float nxr = g_xi[d][tn][j][b_ep];
        float nxz = g_xi[d][tn][512 + j][b_ep];
        float nxn = g_xi[d][tn][1024 + j][b_ep];
        if (tid < 16) {
            while (flags[tid] < e) { }
            __threadfence();             // acquire side
        }
        __syncthreads();
        xr = nxr; xz = nxz; xn = nxn;
    }
}

// ---------------------------------------------------------------------------
// kernel_launch: proj0, zero, zero(dummy), gru0, proj1, gru1, proj2, gru2
// (8 graph nodes; ncu -s 5 -c 1 lands on gru1)
// ---------------------------------------------------------------------------
extern "C" void kernel_launch(void* const* d_in, const int* in_sizes, int n_in,
                              void* d_out, int out_size)
{
    const float* x        = (const float*)d_in[0];
    const float* w_ih_l0  = (const float*)d_in[1];
    const float* w_hh_l0  = (const float*)d_in[2];
    const float* b_ih_l0  = (const float*)d_in[3];
    const float* b_hh_l0  = (const float*)d_in[4];
    const float* w_ih_lr  = (const float*)d_in[5];
    const float* w_hh_lr  = (const float*)d_in[6];
    const float* b_ih_lr  = (const float*)d_in[7];
    const float* b_hh_lr  = (const float*)d_in[8];
    float* out = (float*)d_out;

    const float* WI[LAYERS];
    const float* WH[LAYERS];
    const float* BI[LAYERS];
    const float* BH[LAYERS];
    int KK[LAYERS], SRC[LAYERS], YD[LAYERS];
    for (int L = 0; L < LAYERS; L++) {
        if (L == 0) {
            WI[L] = w_ih_l0; WH[L] = w_hh_l0; BI[L] = b_ih_l0; BH[L] = b_hh_l0;
            KK[L] = 256; SRC[L] = 0;
        } else {
            WI[L] = w_ih_lr + (size_t)(L - 1) * 2 * H3 * 1024;
            WH[L] = w_hh_lr + (size_t)(L - 1) * 2 * H3 * HID;
            BI[L] = b_ih_lr + (L - 1) * 2 * H3;
            BH[L] = b_hh_lr + (L - 1) * 2 * H3;
            KK[L] = 1024; SRC[L] = L;
        }
        YD[L] = (L == 1) ? 1 : 0;   // L0->buf0, L1->buf1, L2->buf0 (unused)
    }

    dim3 pg(H3 / 128, (T_SEQ * BATCH) / 128, 2);
    dim3 gg(16, 4, 2);   // (j-slice, group, dir)

    proj_kernel<<<pg, 256>>>(x, WI[0], BI[0], KK[0], SRC[0]);
    zero_bar_kernel<<<1, 256>>>();
    zero_bar_kernel<<<1, 256>>>();   // dummy: aligns ncu -s 5 on gru1

    gru_layer_kernel<<<gg, 256>>>(WH[0], BH[0], out, 0, YD[0]);
    proj_kernel<<<pg, 256>>>(x, WI[1], BI[1], KK[1], SRC[1]);
    gru_layer_kernel<<<gg, 256>>>(WH[1], BH[1], out, 1, YD[1]);
    proj_kernel<<<pg, 256>>>(x, WI[2], BI[2], KK[2], SRC[2]);
    gru_layer_kernel<<<gg, 256>>>(WH[2], BH[2], out, 2, YD[2]);
}

// round 17
// speedup vs baseline: 1.8463x; 1.2741x over previous
#include <cuda_runtime.h>
#include <cuda_bf16.h>
#include <math.h>

// GRU problem constants
#define T_SEQ 1024
#define BATCH 32
#define HID   512
#define H3    1536   // 3*HID
#define LAYERS 3

typedef unsigned long long ull;

// ---------------------------------------------------------------------------
// Scratch (device globals — no runtime allocation allowed)
// ---------------------------------------------------------------------------
__device__ float g_xi[2][T_SEQ][H3][BATCH];     // [dir][t][gate_row][batch]
__device__ float g_y[2][T_SEQ][BATCH][2 * HID]; // layer outputs (2 buffers)
__device__ float g_h[2][2][BATCH][HID];         // h double buffer [buf][dir][b][k]
__device__ int   g_flag[2][4][32];              // [dir][group][cta] epoch flags
// bf16-split planes for the tensor-core projections
__device__ __nv_bfloat16 g_ah[T_SEQ * BATCH * 1024];      // A hi
__device__ __nv_bfloat16 g_al[T_SEQ * BATCH * 1024];      // A lo
__device__ __nv_bfloat16 g_wh[LAYERS * 2 * H3 * 1024];    // W hi
__device__ __nv_bfloat16 g_wl[LAYERS * 2 * H3 * 1024];    // W lo

// ---------------------------------------------------------------------------
// PTX helpers
// ---------------------------------------------------------------------------
__device__ __forceinline__ void ffma2(ull& d, ull a, ull b) {
    asm("fma.rn.f32x2 %0, %1, %2, %0;" : "+l"(d) : "l"(a), "l"(b));
}
__device__ __forceinline__ float2 unpk(ull v) {
    float2 f; asm("mov.b64 {%0, %1}, %2;" : "=f"(f.x), "=f"(f.y) : "l"(v));
    return f;
}
// Classic warp-level HMMA (sm_80+, no 'a'-target needed): bf16 in, fp32 accum
__device__ __forceinline__ void mma16816(float* c, const unsigned* a,
                                         const unsigned* b) {
    asm volatile(
        "mma.sync.aligned.m16n8k16.row.col.f32.bf16.bf16.f32 "
        "{%0,%1,%2,%3}, {%4,%5,%6,%7}, {%8,%9}, {%0,%1,%2,%3};"
        : "+f"(c[0]), "+f"(c[1]), "+f"(c[2]), "+f"(c[3])
        : "r"(a[0]), "r"(a[1]), "r"(a[2]), "r"(a[3]),
          "r"(b[0]), "r"(b[1]));
}

// ---------------------------------------------------------------------------
// Zero the flag array
// ---------------------------------------------------------------------------
__global__ void zero_bar_kernel() {
    int i = threadIdx.x;
    if (i < 2 * 4 * 32) ((int*)g_flag)[i] = 0;
}

// ---------------------------------------------------------------------------
// bf16 split conversion: hi = bf16(v), lo = bf16(v - hi)
// ---------------------------------------------------------------------------
__device__ __forceinline__ void split4(float4 v, __nv_bfloat16* hi,
                                       __nv_bfloat16* lo) {
    __nv_bfloat16 h0 = __float2bfloat16(v.x);
    __nv_bfloat16 h1 = __float2bfloat16(v.y);
    __nv_bfloat16 h2 = __float2bfloat16(v.z);
    __nv_bfloat16 h3 = __float2bfloat16(v.w);
    hi[0] = h0; hi[1] = h1; hi[2] = h2; hi[3] = h3;
    lo[0] = __float2bfloat16(v.x - __bfloat162float(h0));
    lo[1] = __float2bfloat16(v.y - __bfloat162float(h1));
    lo[2] = __float2bfloat16(v.z - __bfloat162float(h2));
    lo[3] = __float2bfloat16(v.w - __bfloat162float(h3));
}

__global__ void conv_a_kernel(const float* __restrict__ x0, int src, int n4) {
    const float* A = (src == 0) ? x0 : &g_y[src - 1][0][0][0];
    int i = blockIdx.x * blockDim.x + threadIdx.x;
    if (i < n4) {
        float4 v = *(const float4*)&A[(size_t)i * 4];
        split4(v, &g_ah[(size_t)i * 4], &g_al[(size_t)i * 4]);
    }
}

__global__ void conv_w_kernel(const float* __restrict__ w, size_t off, int n4) {
    int i = blockIdx.x * blockDim.x + threadIdx.x;
    if (i < n4) {
        float4 v = *(const float4*)&w[(size_t)i * 4];
        split4(v, &g_wh[off + (size_t)i * 4], &g_wl[off + (size_t)i * 4]);
    }
}

// ---------------------------------------------------------------------------
// HMMA projection: Xi[d][t][g][b] = sum_k A[m][k]*W[d][g][k] + bias
// CTA: 256 threads = 8 warps (4m x 2n), tile 128m x 64n, K chunks of 64.
// bf16 split: D += Ah*Bh + Ah*Bl + Al*Bh  (3 HMMAs per fragment pair).
// smem rows padded to 72 bf16 (144B): bank(row r, lane tig) = 4r+tig mod 32
// -> every b32 fragment load is conflict-free.
// ---------------------------------------------------------------------------
#define KC    64
#define PROW  72                       // padded row length (bf16)
#define S_AH  0
#define S_AL  (128 * PROW * 2)         // 18432
#define S_BH  (2 * 128 * PROW * 2)     // 36864
#define S_BL  (S_BH + 64 * PROW * 2)   // 46080
#define S_TOT (S_BL + 64 * PROW * 2)   // 55296 bytes (dynamic smem)

__global__ __launch_bounds__(256) void proj_mma_kernel(
    const __nv_bfloat16* __restrict__ Wh,   // layer-offset W hi [2][1536][K]
    const __nv_bfloat16* __restrict__ Wl,
    const float* __restrict__ bih,          // (2, 1536)
    int K)
{
    extern __shared__ char sm[];
    __nv_bfloat16* sAh = (__nv_bfloat16*)(sm + S_AH);
    __nv_bfloat16* sAl = (__nv_bfloat16*)(sm + S_AL);
    __nv_bfloat16* sBh = (__nv_bfloat16*)(sm + S_BH);
    __nv_bfloat16* sBl = (__nv_bfloat16*)(sm + S_BL);

    int tid  = threadIdx.x;
    int wid  = tid >> 5;
    int lane = tid & 31;
    int g    = lane >> 2;              // groupID
    int tig  = lane & 3;               // threadID_in_group
    int wm   = wid & 3;                // warp m index (4)
    int wn   = wid >> 2;               // warp n index (2)
    int n0   = blockIdx.x * 64;        // gate-row tile
    int m0   = blockIdx.y * 128;       // (t,b) row tile
    int d    = blockIdx.z;

    const __nv_bfloat16* Wdh = Wh + (size_t)d * H3 * K;
    const __nv_bfloat16* Wdl = Wl + (size_t)d * H3 * K;

    float acc[2][4][4];
#pragma unroll
    for (int mf = 0; mf < 2; mf++)
#pragma unroll
        for (int jn = 0; jn < 4; jn++)
#pragma unroll
            for (int q = 0; q < 4; q++) acc[mf][jn][q] = 0.f;

    int nchunks = K / KC;
    for (int c = 0; c < nchunks; c++) {
        int kc = c * KC;
        // Stage A planes: 128 rows x 8 uint4 = 1024 uint4 -> 4 iters
#pragma unroll
        for (int it = 0; it < 4; it++) {
            int idx = it * 256 + tid;
            int r   = idx >> 3;
            int cu  = idx & 7;
            size_t go = (size_t)(m0 + r) * K + kc + cu * 8;
            *(uint4*)&sAh[r * PROW + cu * 8] = *(const uint4*)&g_ah[go];
            *(uint4*)&sAl[r * PROW + cu * 8] = *(const uint4*)&g_al[go];
        }
        // Stage B planes: 64 rows x 8 uint4 = 512 uint4 -> 2 iters
#pragma unroll
        for (int it = 0; it < 2; it++) {
            int idx = it * 256 + tid;
            int r   = idx >> 3;
            int cu  = idx & 7;
            size_t go = (size_t)(n0 + r) * K + kc + cu * 8;
            *(uint4*)&sBh[r * PROW + cu * 8] = *(const uint4*)&Wdh[go];
            *(uint4*)&sBl[r * PROW + cu * 8] = *(const uint4*)&Wdl[go];
        }
        __syncthreads();

#pragma unroll
        for (int kk = 0; kk < KC; kk += 16) {
            // A fragments (hi, lo) for both 16-row m-frags
            unsigned ah[2][4], al[2][4];
#pragma unroll
            for (int mf = 0; mf < 2; mf++) {
                int rb = wm * 32 + mf * 16;
                const __nv_bfloat16* ph = &sAh[(rb + g) * PROW + kk + tig * 2];
                const __nv_bfloat16* pl = &sAl[(rb + g) * PROW + kk + tig * 2];
                ah[mf][0] = *(const unsigned*)ph;
                ah[mf][1] = *(const unsigned*)(ph + 8 * PROW);
                ah[mf][2] = *(const unsigned*)(ph + 8);
                ah[mf][3] = *(const unsigned*)(ph + 8 * PROW + 8);
                al[mf][0] = *(const unsigned*)pl;
                al[mf][1] = *(const unsigned*)(pl + 8 * PROW);
                al[mf][2] = *(const unsigned*)(pl + 8);
                al[mf][3] = *(const unsigned*)(pl + 8 * PROW + 8);
            }
            // B fragments (hi, lo) for the 4 8-col n-frags
            unsigned bh[4][2], bl[4][2];
#pragma unroll
            for (int jn = 0; jn < 4; jn++) {
                int nr = wn * 32 + jn * 8 + g;     // W row (gate index)
                const __nv_bfloat16* ph = &sBh[nr * PROW + kk + tig * 2];
                const __nv_bfloat16* pl = &sBl[nr * PROW + kk + tig * 2];
                bh[jn][0] = *(const unsigned*)ph;
                bh[jn][1] = *(const unsigned*)(ph + 8);
                bl[jn][0] = *(const unsigned*)pl;
                bl[jn][1] = *(const unsigned*)(pl + 8);
            }
#pragma unroll
            for (int mf = 0; mf < 2; mf++)
#pragma unroll
                for (int jn = 0; jn < 4; jn++) {
                    mma16816(acc[mf][jn], ah[mf], bh[jn]);   // hi*hi
                    mma16816(acc[mf][jn], ah[mf], bl[jn]);   // hi*lo
                    mma16816(acc[mf][jn], al[mf], bh[jn]);   // lo*hi
                }
        }
        __syncthreads();
    }

    // Epilogue: c0,c1 -> (row g, cols tig*2, +1); c2,c3 -> (row g+8)
    const float* bp = bih + d * H3;
#pragma unroll
    for (int mf = 0; mf < 2; mf++) {
        int m1 = m0 + wm * 32 + mf * 16 + g;
        int m2 = m1 + 8;
        int t1 = m1 >> 5, b1 = m1 & 31;
        int t2 = m2 >> 5, b2 = m2 & 31;
#pragma unroll
        for (int jn = 0; jn < 4; jn++) {
            int gc = n0 + wn * 32 + jn * 8 + tig * 2;
            float bb0 = bp[gc], bb1 = bp[gc + 1];
            g_xi[d][t1][gc][b1]     = acc[mf][jn][0] + bb0;
            g_xi[d][t1][gc + 1][b1] = acc[mf][jn][1] + bb1;
            g_xi[d][t2][gc][b2]     = acc[mf][jn][2] + bb0;
            g_xi[d][t2][gc + 1][b2] = acc[mf][jn][3] + bb1;
        }
    }
}

// ---------------------------------------------------------------------------
// Persistent recurrent kernel (R15 exact — best measured: 4.81ms/layer).
// ---------------------------------------------------------------------------
__global__ __launch_bounds__(256) void gru_layer_kernel(
    const float* __restrict__ whh,   // (2, 1536, 512)
    const float* __restrict__ bhh,   // (2, 1536)
    float* __restrict__ dout,        // (6, 32, 512)
    int layer, int ydst)
{
    __shared__ float sH[8 * HID];

    int ctax = blockIdx.x;
    int grp  = blockIdx.y;
    int d    = blockIdx.z;
    int tid  = threadIdx.x;
    int w    = tid >> 5;
    int l    = tid & 31;
    int lj   = l & 3;
    int lks  = l >> 2;
    int j    = ctax * 32 + w * 4 + lj;
    int b_ep = grp * 8 + lks;

    ull Wr[32], Wz[32], Wn[32];
    {
        const float* wd = whh + (size_t)d * H3 * HID;
        const float* pr = &wd[(size_t)(0 * 512 + j) * 512 + lks * 4];
        const float* pz = &wd[(size_t)(1 * 512 + j) * 512 + lks * 4];
        const float* pn = &wd[(size_t)(2 * 512 + j) * 512 + lks * 4];
#pragma unroll
        for (int i = 0; i < 16; i++) {
            ulonglong2 v;
            v = *(const ulonglong2*)&pr[i * 32];
            Wr[2 * i] = v.x; Wr[2 * i + 1] = v.y;
            v = *(const ulonglong2*)&pz[i * 32];
            Wz[2 * i] = v.x; Wz[2 * i + 1] = v.y;
            v = *(const ulonglong2*)&pn[i * 32];
            Wn[2 * i] = v.x; Wn[2 * i + 1] = v.y;
        }
    }
    const float* bd = bhh + d * H3;
    float br = bd[j], bz = bd[512 + j], bn = bd[1024 + j];

    volatile int* flags = &g_flag[d][grp][0];
    float hold = 0.f;
    int t0 = d ? (T_SEQ - 1) : 0;
    float xr = g_xi[d][t0][j][b_ep];
    float xz = g_xi[d][t0][512 + j][b_ep];
    float xn = g_xi[d][t0][1024 + j][b_ep];

    for (int s = 0; s < T_SEQ; s++) {
        int t = d ? (T_SEQ - 1 - s) : s;

        float arS = 0.f, azS = 0.f, anS = 0.f;
        if (s > 0) {
            const float* hin = &g_h[s & 1][d][grp * 8][0];
#pragma unroll
            for (int it = 0; it < 4; it++) {
                int idx = it * 256 + tid;
                float4 v = __ldcg((const float4*)&hin[idx << 2]);
                *(float4*)&sH[idx << 2] = v;
            }
            __syncthreads();

#pragma unroll
            for (int bp = 0; bp < 4; bp++) {
                int bA = bp * 2, bB = bp * 2 + 1;
                const float* hpA = &sH[bA * HID + lks * 4];
                const float* hpB = &sH[bB * HID + lks * 4];
                ull aA0 = 0ull, aA1 = 0ull, aA2 = 0ull;
                ull aB0 = 0ull, aB1 = 0ull, aB2 = 0ull;
#pragma unroll
                for (int i = 0; i < 16; i++) {
                    ulonglong2 hA = *(const ulonglong2*)&hpA[i * 32];
                    ulonglong2 hB = *(const ulonglong2*)&hpB[i * 32];
                    ffma2(aA0, Wr[2 * i], hA.x); ffma2(aA0, Wr[2 * i + 1], hA.y);
                    ffma2(aB0, Wr[2 * i], hB.x); ffma2(aB0, Wr[2 * i + 1], hB.y);
                    ffma2(aA1, Wz[2 * i], hA.x); ffma2(aA1, Wz[2 * i + 1], hA.y);
                    ffma2(aB1, Wz[2 * i], hB.x); ffma2(aB1, Wz[2 * i + 1], hB.y);
                    ffma2(aA2, Wn[2 * i], hA.x); ffma2(aA2, Wn[2 * i + 1], hA.y);
                    ffma2(aB2, Wn[2 * i], hB.x); ffma2(aB2, Wn[2 * i + 1], hB.y);
                }
                float2 f;
                f = unpk(aA0); float arA = f.x + f.y;
                f = unpk(aA1); float azA = f.x + f.y;
                f = unpk(aA2); float anA = f.x + f.y;
                f = unpk(aB0); float arB = f.x + f.y;
                f = unpk(aB1); float azB = f.x + f.y;
                f = unpk(aB2); float anB = f.x + f.y;
#pragma unroll
                for (int m = 4; m <= 16; m <<= 1) {
                    arA += __shfl_xor_sync(0xffffffffu, arA, m);
                    azA += __shfl_xor_sync(0xffffffffu, azA, m);
                    anA += __shfl_xor_sync(0xffffffffu, anA, m);
                    arB += __shfl_xor_sync(0xffffffffu, arB, m);
                    azB += __shfl_xor_sync(0xffffffffu, azB, m);
                    anB += __shfl_xor_sync(0xffffffffu, anB, m);
                }
                if (lks == bA) { arS = arA; azS = azA; anS = anA; }
                if (lks == bB) { arS = arB; azS = azB; anS = anB; }
            }
        }

        float r = 1.f / (1.f + __expf(-(xr + arS + br)));
        float z = 1.f / (1.f + __expf(-(xz + azS + bz)));
        float n = tanhf(xn + r * (anS + bn));
        float hnew = (1.f - z) * n + z * hold;
        hold = hnew;

        g_h[(s & 1) ^ 1][d][b_ep][j] = hnew;
        g_y[ydst][t][b_ep][d * HID + j] = hnew;

        if (s == T_SEQ - 1) {
            dout[((layer * 2 + d) * BATCH + b_ep) * HID + j] = hnew;
            break;
        }

        __syncthreads();
        int e = layer * T_SEQ + s + 1;
        if (tid == 0) {
            __threadfence();
            flags[ctax] = e;
        }
        int tn = d ? (T_SEQ - 2 - s) : (s + 1);
        float nxr = g_xi[d][tn][j][b_ep];
        float nxz = g_xi[d][tn][512 + j][b_ep];
        float nxn = g_xi[d][tn][1024 + j][b_ep];
        if (tid < 16) {
            while (flags[tid] < e) { }
            __threadfence();
        }
        __syncthreads();
        xr = nxr; xz = nxz; xn = nxn;
    }
}

// ---------------------------------------------------------------------------
// kernel_launch: zero, convW x3, then per layer: convA, proj, gru
// ---------------------------------------------------------------------------
extern "C" void kernel_launch(void* const* d_in, const int* in_sizes, int n_in,
                              void* d_out, int out_size)
{
    const float* x        = (const float*)d_in[0];
    const float* w_ih_l0  = (const float*)d_in[1];
    const float* w_hh_l0  = (const float*)d_in[2];
    const float* b_ih_l0  = (const float*)d_in[3];
    const float* b_hh_l0  = (const float*)d_in[4];
    const float* w_ih_lr  = (const float*)d_in[5];
    const float* w_hh_lr  = (const float*)d_in[6];
    const float* b_ih_lr  = (const float*)d_in[7];
    const float* b_hh_lr  = (const float*)d_in[8];
    float* out = (float*)d_out;

    cudaFuncSetAttribute(proj_mma_kernel,
                         cudaFuncAttributeMaxDynamicSharedMemorySize, S_TOT);

    const float* WI[LAYERS];
    const float* WH[LAYERS];
    const float* BI[LAYERS];
    const float* BH[LAYERS];
    int KK[LAYERS], SRC[LAYERS], YD[LAYERS];
    size_t WOFF[LAYERS];
    for (int L = 0; L < LAYERS; L++) {
        if (L == 0) {
            WI[L] = w_ih_l0; WH[L] = w_hh_l0; BI[L] = b_ih_l0; BH[L] = b_hh_l0;
            KK[L] = 256; SRC[L] = 0;
        } else {
            WI[L] = w_ih_lr + (size_t)(L - 1) * 2 * H3 * 1024;
            WH[L] = w_hh_lr + (size_t)(L - 1) * 2 * H3 * HID;
            BI[L] = b_ih_lr + (L - 1) * 2 * H3;
            BH[L] = b_hh_lr + (L - 1) * 2 * H3;
            KK[L] = 1024; SRC[L] = L;
        }
        YD[L]   = (L == 1) ? 1 : 0;
        WOFF[L] = (size_t)L * 2 * H3 * 1024;
    }

    dim3 gg(16, 4, 2);   // gru: (j-slice, group, dir)

    zero_bar_kernel<<<1, 256>>>();
    for (int L = 0; L < LAYERS; L++) {
        int n4 = 2 * H3 * KK[L] / 4;
        conv_w_kernel<<<(n4 + 255) / 256, 256>>>(WI[L], WOFF[L], n4);
    }

    void* whp = nullptr; void* wlp = nullptr;
    cudaGetSymbolAddress(&whp, g_wh);
    cudaGetSymbolAddress(&wlp, g_wl);

    for (int L = 0; L < LAYERS; L++) {
        int K = KK[L];
        int n4a = T_SEQ * BATCH * K / 4;
        conv_a_kernel<<<(n4a + 255) / 256, 256>>>(x, SRC[L], n4a);

        dim3 pg(H3 / 64, (T_SEQ * BATCH) / 128, 2);
        proj_mma_kernel<<<pg, 256, S_TOT>>>(
            (const __nv_bfloat16*)whp + WOFF[L],
            (const __nv_bfloat16*)wlp + WOFF[L],
            BI[L], K);

        gru_layer_kernel<<<gg, 256>>>(WH[L], BH[L], out, L, YD[L]);
    }
}